// round 1
// baseline (speedup 1.0000x reference)
#include <cuda_runtime.h>
#include <math.h>

#define BB 2
#define SS 1024
#define DD 1024
#define HH 16
#define HDD 64

// ---------------- scratch (device globals; no allocation allowed) ----------
__device__ float g_q[BB*HH*SS*HDD];          // [bh, l, d]  8MB
__device__ float g_k[BB*HH*SS*HDD];          // [bh, r, d]  8MB
__device__ float g_v[BB*HH*SS*HDD];          // [bh, r, d]  8MB
__device__ float g_sc[(size_t)BB*HH*SS*SS];  // scores -> probs (in place) 128MB

// ============================================================================
// K1: q/k/v = X @ W^T + b, written in [B,H,S,HD] layout.
// 128x128 tile, BK=16, 256 threads, 8x8 per thread.
// ============================================================================
__global__ __launch_bounds__(256, 2)
void qkv_kernel(const float* __restrict__ X,
                const float* __restrict__ Wq, const float* __restrict__ bq,
                const float* __restrict__ Wk, const float* __restrict__ bk,
                const float* __restrict__ Wv, const float* __restrict__ bv)
{
    const int z = blockIdx.z;
    const float* W    = (z == 0) ? Wq : (z == 1) ? Wk : Wv;
    const float* bias = (z == 0) ? bq : (z == 1) ? bk : bv;
    float* dst        = (z == 0) ? g_q : (z == 1) ? g_k : g_v;

    __shared__ float As[16][128];
    __shared__ float Bs[16][128];

    const int tid = threadIdx.x;
    const int tx = tid & 15, ty = tid >> 4;
    const int m0 = blockIdx.y * 128;   // token rows
    const int n0 = blockIdx.x * 128;   // output cols

    float acc[8][8];
#pragma unroll
    for (int i = 0; i < 8; i++)
#pragma unroll
        for (int j = 0; j < 8; j++) acc[i][j] = 0.f;

    for (int k0 = 0; k0 < 1024; k0 += 16) {
#pragma unroll
        for (int r = 0; r < 2; r++) {
            int idx = r * 256 + tid;        // 0..511
            int row = idx >> 2;             // 0..127
            int c4  = (idx & 3) * 4;        // 0,4,8,12
            float4 va = *(const float4*)&X[(size_t)(m0 + row) * 1024 + k0 + c4];
            As[c4 + 0][row] = va.x; As[c4 + 1][row] = va.y;
            As[c4 + 2][row] = va.z; As[c4 + 3][row] = va.w;
            float4 vb = *(const float4*)&W[(size_t)(n0 + row) * 1024 + k0 + c4];
            Bs[c4 + 0][row] = vb.x; Bs[c4 + 1][row] = vb.y;
            Bs[c4 + 2][row] = vb.z; Bs[c4 + 3][row] = vb.w;
        }
        __syncthreads();
#pragma unroll
        for (int k = 0; k < 16; k++) {
            float a[8], b[8];
#pragma unroll
            for (int u = 0; u < 8; u++) a[u] = As[k][ty * 8 + u];
#pragma unroll
            for (int u = 0; u < 8; u++) b[u] = Bs[k][tx * 8 + u];
#pragma unroll
            for (int i = 0; i < 8; i++)
#pragma unroll
                for (int j = 0; j < 8; j++)
                    acc[i][j] = fmaf(a[i], b[j], acc[i][j]);
        }
        __syncthreads();
    }

#pragma unroll
    for (int j = 0; j < 8; j++) {
        int nc = n0 + tx * 8 + j;
        float bval = bias[nc];
        int h = nc >> 6, dd = nc & 63;
#pragma unroll
        for (int i = 0; i < 8; i++) {
            int m = m0 + ty * 8 + i;
            int b_ = m >> 10, l = m & 1023;
            dst[(((size_t)(b_ * HH + h)) * SS + l) * HDD + dd] = acc[i][j] + bval;
        }
    }
}

// ============================================================================
// K2: scores[bh,l,r] = (q[l]·k[r] + q[l]·E[l-r+1023]) * 0.125 + mask[b,r]
// 128x128 tile, full HD=64 processed in 4 chunks of 16, 8x8 per thread.
// E rows for the tile span 255 consecutive dist_emb rows, indexed by diagonal.
// ============================================================================
__global__ __launch_bounds__(256)
void scores_kernel(const float* __restrict__ mask, const float* __restrict__ de)
{
    __shared__ float Qs[16 * 128];
    __shared__ float Ks[16 * 128];
    __shared__ float Es[16 * 256];

    const int tid = threadIdx.x;
    const int tx = tid & 15, ty = tid >> 4;
    const int bh = blockIdx.z;
    const int l0 = blockIdx.y * 128;
    const int r0 = blockIdx.x * 128;
    const int b_ = bh >> 4;
    const int jb = l0 - r0 + 896;  // first dist_emb row needed (255 rows total)

    const float* qg = g_q + (size_t)bh * SS * HDD;
    const float* kg = g_k + (size_t)bh * SS * HDD;

    float acc[8][8];
#pragma unroll
    for (int i = 0; i < 8; i++)
#pragma unroll
        for (int j = 0; j < 8; j++) acc[i][j] = 0.f;

    const int ebase = (ty - tx) * 8 + 127;  // diagonal base: t = ebase + (ii - jj)

    for (int c = 0; c < 4; c++) {
        const int kb = c * 16;
        // Q,K chunk: 128 x 16 each (512 float4 -> 2 per thread)
#pragma unroll
        for (int rep = 0; rep < 2; rep++) {
            int idx = rep * 256 + tid;
            int li = idx & 127;
            int k4 = (idx >> 7) * 4;  // 0,4,8,12
            float4 vq = *(const float4*)&qg[(size_t)(l0 + li) * 64 + kb + k4];
            Qs[(k4 + 0) * 128 + li] = vq.x; Qs[(k4 + 1) * 128 + li] = vq.y;
            Qs[(k4 + 2) * 128 + li] = vq.z; Qs[(k4 + 3) * 128 + li] = vq.w;
            float4 vk = *(const float4*)&kg[(size_t)(r0 + li) * 64 + kb + k4];
            Ks[(k4 + 0) * 128 + li] = vk.x; Ks[(k4 + 1) * 128 + li] = vk.y;
            Ks[(k4 + 2) * 128 + li] = vk.z; Ks[(k4 + 3) * 128 + li] = vk.w;
        }
        // E chunk: 255 x 16
#pragma unroll
        for (int rep = 0; rep < 4; rep++) {
            int idx = rep * 256 + tid;
            int t = idx & 255;
            int k4 = (idx >> 8) * 4;  // 0,4,8,12
            if (t < 255) {
                float4 ve = *(const float4*)&de[(size_t)(jb + t) * 64 + kb + k4];
                Es[(k4 + 0) * 256 + t] = ve.x; Es[(k4 + 1) * 256 + t] = ve.y;
                Es[(k4 + 2) * 256 + t] = ve.z; Es[(k4 + 3) * 256 + t] = ve.w;
            }
        }
        __syncthreads();

        for (int k = 0; k < 16; k++) {
            float a[8], b[8], e[15];
#pragma unroll
            for (int u = 0; u < 8; u++) a[u] = Qs[k * 128 + ty * 8 + u];
#pragma unroll
            for (int u = 0; u < 8; u++) b[u] = Ks[k * 128 + tx * 8 + u];
#pragma unroll
            for (int d = 0; d < 15; d++) e[d] = Es[k * 256 + ebase - 7 + d];
#pragma unroll
            for (int i = 0; i < 8; i++)
#pragma unroll
                for (int j = 0; j < 8; j++) {
                    acc[i][j] = fmaf(a[i], b[j], acc[i][j]);
                    acc[i][j] = fmaf(a[i], e[i - j + 7], acc[i][j]);
                }
        }
        __syncthreads();
    }

    float* outp = g_sc + (size_t)bh * SS * SS;
    float mk[8];
#pragma unroll
    for (int j = 0; j < 8; j++) mk[j] = mask[b_ * SS + r0 + tx * 8 + j];
#pragma unroll
    for (int i = 0; i < 8; i++) {
        int l = l0 + ty * 8 + i;
        float4 oA, oB;
        oA.x = fmaf(acc[i][0], 0.125f, mk[0]); oA.y = fmaf(acc[i][1], 0.125f, mk[1]);
        oA.z = fmaf(acc[i][2], 0.125f, mk[2]); oA.w = fmaf(acc[i][3], 0.125f, mk[3]);
        oB.x = fmaf(acc[i][4], 0.125f, mk[4]); oB.y = fmaf(acc[i][5], 0.125f, mk[5]);
        oB.z = fmaf(acc[i][6], 0.125f, mk[6]); oB.w = fmaf(acc[i][7], 0.125f, mk[7]);
        *(float4*)&outp[(size_t)l * SS + r0 + tx * 8]     = oA;
        *(float4*)&outp[(size_t)l * SS + r0 + tx * 8 + 4] = oB;
    }
}

// ============================================================================
// K3: per-row stochastic double softmax (in place in g_sc).
//   w = eps - log(u+eps);  samples = softmax(s+g) via exp(s-m)/w
//   probs = softmax(s + samples) via exp(s-m)*exp(samples-1)  [C2 = m+1]
// One CTA (256 thr) per row; 4 elems per thread (float4).
// ============================================================================
__global__ __launch_bounds__(256)
void softmax_kernel(const float* __restrict__ gum)
{
    __shared__ float red[8];
    __shared__ float bcast;
    const int tid = threadIdx.x;
    const int lane = tid & 31, wid = tid >> 5;

    const size_t row = (size_t)blockIdx.y * SS + blockIdx.x;  // bh*S + l
    float* srow = g_sc + row * SS;
    const float* urow = gum + row * SS;

    float4 s = *(const float4*)&srow[tid * 4];
    float4 u = *(const float4*)&urow[tid * 4];

    // ---- reduction 1: row max of scores ----
    float m = fmaxf(fmaxf(s.x, s.y), fmaxf(s.z, s.w));
#pragma unroll
    for (int o = 16; o; o >>= 1) m = fmaxf(m, __shfl_xor_sync(0xffffffffu, m, o));
    if (lane == 0) red[wid] = m;
    __syncthreads();
    if (tid == 0) {
        float r = red[0];
#pragma unroll
        for (int i = 1; i < 8; i++) r = fmaxf(r, red[i]);
        bcast = r;
    }
    __syncthreads();
    m = bcast;

    float t0 = __expf(s.x - m), t1 = __expf(s.y - m);
    float t2 = __expf(s.z - m), t3 = __expf(s.w - m);
    // accurate logf: MUFU LG2 abs error corrupts w when u -> 1 (w ~ 1e-6)
    float w0 = 1e-10f - logf(u.x + 1e-10f);
    float w1 = 1e-10f - logf(u.y + 1e-10f);
    float w2 = 1e-10f - logf(u.z + 1e-10f);
    float w3 = 1e-10f - logf(u.w + 1e-10f);
    float n0 = __fdividef(t0, w0), n1 = __fdividef(t1, w1);
    float n2 = __fdividef(t2, w2), n3 = __fdividef(t3, w3);

    // ---- reduction 2: sum of samples numerators ----
    float sm1 = (n0 + n1) + (n2 + n3);
    __syncthreads();  // protect red[] reuse
#pragma unroll
    for (int o = 16; o; o >>= 1) sm1 += __shfl_xor_sync(0xffffffffu, sm1, o);
    if (lane == 0) red[wid] = sm1;
    __syncthreads();
    if (tid == 0) {
        float r = red[0];
#pragma unroll
        for (int i = 1; i < 8; i++) r += red[i];
        bcast = r;
    }
    __syncthreads();
    float inv1 = __fdividef(1.0f, bcast);

    // probs numerator: exp(s + samples - (m+1)) = t * exp(samples - 1)
    float p0 = t0 * __expf(fmaf(n0, inv1, -1.0f));
    float p1 = t1 * __expf(fmaf(n1, inv1, -1.0f));
    float p2 = t2 * __expf(fmaf(n2, inv1, -1.0f));
    float p3 = t3 * __expf(fmaf(n3, inv1, -1.0f));

    // ---- reduction 3: sum of probs numerators ----
    float sm2 = (p0 + p1) + (p2 + p3);
    __syncthreads();
#pragma unroll
    for (int o = 16; o; o >>= 1) sm2 += __shfl_xor_sync(0xffffffffu, sm2, o);
    if (lane == 0) red[wid] = sm2;
    __syncthreads();
    if (tid == 0) {
        float r = red[0];
#pragma unroll
        for (int i = 1; i < 8; i++) r += red[i];
        bcast = r;
    }
    __syncthreads();
    float inv2 = __fdividef(1.0f, bcast);

    float4 o4;
    o4.x = p0 * inv2; o4.y = p1 * inv2; o4.z = p2 * inv2; o4.w = p3 * inv2;
    *(float4*)&srow[tid * 4] = o4;
}

// ============================================================================
// K4: out[b,l,h*64+d] = sum_r probs[bh,l,r] * v[bh,r,d]
// BM=128, BN=64(full), BK=32; 256 threads, 8x4 per thread.
// ============================================================================
__global__ __launch_bounds__(256, 2)
void pv_kernel(float* __restrict__ out)
{
    __shared__ float Ps[32 * 129];  // [k][li], pad 129 -> conflict-free
    __shared__ float Vs[32 * 64];   // [k][d]

    const int tid = threadIdx.x;
    const int tx = tid & 15, ty = tid >> 4;
    const int bh = blockIdx.y;
    const int l0 = blockIdx.x * 128;
    const int b_ = bh >> 4, h = bh & 15;

    const float* P = g_sc + (size_t)bh * SS * SS;
    const float* V = g_v + (size_t)bh * SS * HDD;

    float acc[8][4];
#pragma unroll
    for (int i = 0; i < 8; i++)
#pragma unroll
        for (int j = 0; j < 4; j++) acc[i][j] = 0.f;

    for (int k0 = 0; k0 < 1024; k0 += 32) {
#pragma unroll
        for (int rep = 0; rep < 4; rep++) {
            int idx = rep * 256 + tid;      // 0..1023
            int li = idx >> 3;              // 0..127 (coalesced global)
            int k4 = (idx & 7) * 4;         // 0..28
            float4 vp = *(const float4*)&P[(size_t)(l0 + li) * SS + k0 + k4];
            Ps[(k4 + 0) * 129 + li] = vp.x; Ps[(k4 + 1) * 129 + li] = vp.y;
            Ps[(k4 + 2) * 129 + li] = vp.z; Ps[(k4 + 3) * 129 + li] = vp.w;
        }
#pragma unroll
        for (int rep = 0; rep < 2; rep++) {
            int idx = rep * 256 + tid;      // 0..511
            int kk = idx >> 4;              // 0..31
            int d4 = (idx & 15) * 4;
            *(float4*)&Vs[kk * 64 + d4] =
                *(const float4*)&V[(size_t)(k0 + kk) * 64 + d4];
        }
        __syncthreads();
#pragma unroll 4
        for (int k = 0; k < 32; k++) {
            float a[8];
#pragma unroll
            for (int u = 0; u < 8; u++) a[u] = Ps[k * 129 + ty * 8 + u];
            float4 bv4 = *(const float4*)&Vs[k * 64 + tx * 4];
#pragma unroll
            for (int i = 0; i < 8; i++) {
                acc[i][0] = fmaf(a[i], bv4.x, acc[i][0]);
                acc[i][1] = fmaf(a[i], bv4.y, acc[i][1]);
                acc[i][2] = fmaf(a[i], bv4.z, acc[i][2]);
                acc[i][3] = fmaf(a[i], bv4.w, acc[i][3]);
            }
        }
        __syncthreads();
    }

#pragma unroll
    for (int i = 0; i < 8; i++) {
        int l = l0 + ty * 8 + i;
        float4 o4;
        o4.x = acc[i][0]; o4.y = acc[i][1]; o4.z = acc[i][2]; o4.w = acc[i][3];
        *(float4*)&out[((size_t)(b_ * SS) + l) * DD + h * 64 + tx * 4] = o4;
    }
}

// ============================================================================
extern "C" void kernel_launch(void* const* d_in, const int* in_sizes, int n_in,
                              void* d_out, int out_size)
{
    const float* hidden = (const float*)d_in[0];
    const float* mask   = (const float*)d_in[1];
    const float* gum    = (const float*)d_in[2];
    const float* Wq     = (const float*)d_in[3];
    const float* bq     = (const float*)d_in[4];
    const float* Wk     = (const float*)d_in[5];
    const float* bk     = (const float*)d_in[6];
    const float* Wv     = (const float*)d_in[7];
    const float* bv     = (const float*)d_in[8];
    const float* de     = (const float*)d_in[9];
    float* out = (float*)d_out;

    qkv_kernel<<<dim3(8, 16, 3), 256>>>(hidden, Wq, bq, Wk, bk, Wv, bv);
    scores_kernel<<<dim3(8, 8, 32), 256>>>(mask, de);
    softmax_kernel<<<dim3(1024, 32), 256>>>(gum);
    pv_kernel<<<dim3(8, 32), 256>>>(out);
}

// round 2
// speedup vs baseline: 1.0006x; 1.0006x over previous
#include <cuda_runtime.h>
#include <math.h>

#define BB 2
#define SS 1024
#define DD 1024
#define HH 16
#define HDD 64

// ---------------- scratch (device globals; no allocation allowed) ----------
__device__ float g_q[BB*HH*SS*HDD];          // [bh, l, d]  8MB
__device__ float g_k[BB*HH*SS*HDD];          // [bh, r, d]  8MB
__device__ float g_v[BB*HH*SS*HDD];          // [bh, r, d]  8MB
__device__ float g_sc[(size_t)BB*HH*SS*SS];  // scores -> probs (in place) 128MB

// ============================================================================
// K1: q/k/v = X @ W^T + b, written in [B,H,S,HD] layout.
// 128x128 tile, BK=16, 256 threads, 8x8 per thread.
// ============================================================================
__global__ __launch_bounds__(256, 2)
void qkv_kernel(const float* __restrict__ X,
                const float* __restrict__ Wq, const float* __restrict__ bq,
                const float* __restrict__ Wk, const float* __restrict__ bk,
                const float* __restrict__ Wv, const float* __restrict__ bv)
{
    const int z = blockIdx.z;
    const float* W    = (z == 0) ? Wq : (z == 1) ? Wk : Wv;
    const float* bias = (z == 0) ? bq : (z == 1) ? bk : bv;
    float* dst        = (z == 0) ? g_q : (z == 1) ? g_k : g_v;

    __shared__ float As[16][128];
    __shared__ float Bs[16][128];

    const int tid = threadIdx.x;
    const int tx = tid & 15, ty = tid >> 4;
    const int m0 = blockIdx.y * 128;   // token rows
    const int n0 = blockIdx.x * 128;   // output cols

    float acc[8][8];
#pragma unroll
    for (int i = 0; i < 8; i++)
#pragma unroll
        for (int j = 0; j < 8; j++) acc[i][j] = 0.f;

    for (int k0 = 0; k0 < 1024; k0 += 16) {
#pragma unroll
        for (int r = 0; r < 2; r++) {
            int idx = r * 256 + tid;        // 0..511
            int row = idx >> 2;             // 0..127
            int c4  = (idx & 3) * 4;        // 0,4,8,12
            float4 va = *(const float4*)&X[(size_t)(m0 + row) * 1024 + k0 + c4];
            As[c4 + 0][row] = va.x; As[c4 + 1][row] = va.y;
            As[c4 + 2][row] = va.z; As[c4 + 3][row] = va.w;
            float4 vb = *(const float4*)&W[(size_t)(n0 + row) * 1024 + k0 + c4];
            Bs[c4 + 0][row] = vb.x; Bs[c4 + 1][row] = vb.y;
            Bs[c4 + 2][row] = vb.z; Bs[c4 + 3][row] = vb.w;
        }
        __syncthreads();
#pragma unroll
        for (int k = 0; k < 16; k++) {
            float a[8], b[8];
#pragma unroll
            for (int u = 0; u < 8; u++) a[u] = As[k][ty * 8 + u];
#pragma unroll
            for (int u = 0; u < 8; u++) b[u] = Bs[k][tx * 8 + u];
#pragma unroll
            for (int i = 0; i < 8; i++)
#pragma unroll
                for (int j = 0; j < 8; j++)
                    acc[i][j] = fmaf(a[i], b[j], acc[i][j]);
        }
        __syncthreads();
    }

#pragma unroll
    for (int j = 0; j < 8; j++) {
        int nc = n0 + tx * 8 + j;
        float bval = bias[nc];
        int h = nc >> 6, dd = nc & 63;
#pragma unroll
        for (int i = 0; i < 8; i++) {
            int m = m0 + ty * 8 + i;
            int b_ = m >> 10, l = m & 1023;
            dst[(((size_t)(b_ * HH + h)) * SS + l) * HDD + dd] = acc[i][j] + bval;
        }
    }
}

// ============================================================================
// K2: scores[bh,l,r] = (q[l]·k[r] + q[l]·E[l-r+1023]) * 0.125 + mask[b,r]
// 128x128 tile, full HD=64 processed in 4 chunks of 16, 8x8 per thread.
// E rows for the tile span 255 consecutive dist_emb rows, indexed by diagonal.
// ============================================================================
__global__ __launch_bounds__(256)
void scores_kernel(const float* __restrict__ mask, const float* __restrict__ de)
{
    __shared__ float Qs[16 * 128];
    __shared__ float Ks[16 * 128];
    __shared__ float Es[16 * 256];

    const int tid = threadIdx.x;
    const int tx = tid & 15, ty = tid >> 4;
    const int bh = blockIdx.z;
    const int l0 = blockIdx.y * 128;
    const int r0 = blockIdx.x * 128;
    const int b_ = bh >> 4;
    const int jb = l0 - r0 + 896;  // first dist_emb row needed (255 rows total)

    const float* qg = g_q + (size_t)bh * SS * HDD;
    const float* kg = g_k + (size_t)bh * SS * HDD;

    float acc[8][8];
#pragma unroll
    for (int i = 0; i < 8; i++)
#pragma unroll
        for (int j = 0; j < 8; j++) acc[i][j] = 0.f;

    const int ebase = (ty - tx) * 8 + 127;  // diagonal base: t = ebase + (ii - jj)

    for (int c = 0; c < 4; c++) {
        const int kb = c * 16;
        // Q,K chunk: 128 x 16 each (512 float4 -> 2 per thread)
#pragma unroll
        for (int rep = 0; rep < 2; rep++) {
            int idx = rep * 256 + tid;
            int li = idx & 127;
            int k4 = (idx >> 7) * 4;  // 0,4,8,12
            float4 vq = *(const float4*)&qg[(size_t)(l0 + li) * 64 + kb + k4];
            Qs[(k4 + 0) * 128 + li] = vq.x; Qs[(k4 + 1) * 128 + li] = vq.y;
            Qs[(k4 + 2) * 128 + li] = vq.z; Qs[(k4 + 3) * 128 + li] = vq.w;
            float4 vk = *(const float4*)&kg[(size_t)(r0 + li) * 64 + kb + k4];
            Ks[(k4 + 0) * 128 + li] = vk.x; Ks[(k4 + 1) * 128 + li] = vk.y;
            Ks[(k4 + 2) * 128 + li] = vk.z; Ks[(k4 + 3) * 128 + li] = vk.w;
        }
        // E chunk: 255 x 16
#pragma unroll
        for (int rep = 0; rep < 4; rep++) {
            int idx = rep * 256 + tid;
            int t = idx & 255;
            int k4 = (idx >> 8) * 4;  // 0,4,8,12
            if (t < 255) {
                float4 ve = *(const float4*)&de[(size_t)(jb + t) * 64 + kb + k4];
                Es[(k4 + 0) * 256 + t] = ve.x; Es[(k4 + 1) * 256 + t] = ve.y;
                Es[(k4 + 2) * 256 + t] = ve.z; Es[(k4 + 3) * 256 + t] = ve.w;
            }
        }
        __syncthreads();

        for (int k = 0; k < 16; k++) {
            float a[8], b[8], e[15];
#pragma unroll
            for (int u = 0; u < 8; u++) a[u] = Qs[k * 128 + ty * 8 + u];
#pragma unroll
            for (int u = 0; u < 8; u++) b[u] = Ks[k * 128 + tx * 8 + u];
#pragma unroll
            for (int d = 0; d < 15; d++) e[d] = Es[k * 256 + ebase - 7 + d];
#pragma unroll
            for (int i = 0; i < 8; i++)
#pragma unroll
                for (int j = 0; j < 8; j++) {
                    acc[i][j] = fmaf(a[i], b[j], acc[i][j]);
                    acc[i][j] = fmaf(a[i], e[i - j + 7], acc[i][j]);
                }
        }
        __syncthreads();
    }

    float* outp = g_sc + (size_t)bh * SS * SS;
    float mk[8];
#pragma unroll
    for (int j = 0; j < 8; j++) mk[j] = mask[b_ * SS + r0 + tx * 8 + j];
#pragma unroll
    for (int i = 0; i < 8; i++) {
        int l = l0 + ty * 8 + i;
        float4 oA, oB;
        oA.x = fmaf(acc[i][0], 0.125f, mk[0]); oA.y = fmaf(acc[i][1], 0.125f, mk[1]);
        oA.z = fmaf(acc[i][2], 0.125f, mk[2]); oA.w = fmaf(acc[i][3], 0.125f, mk[3]);
        oB.x = fmaf(acc[i][4], 0.125f, mk[4]); oB.y = fmaf(acc[i][5], 0.125f, mk[5]);
        oB.z = fmaf(acc[i][6], 0.125f, mk[6]); oB.w = fmaf(acc[i][7], 0.125f, mk[7]);
        *(float4*)&outp[(size_t)l * SS + r0 + tx * 8]     = oA;
        *(float4*)&outp[(size_t)l * SS + r0 + tx * 8 + 4] = oB;
    }
}

// ============================================================================
// K3: per-row stochastic double softmax (in place in g_sc).
//   w = eps - log(u+eps);  samples = softmax(s+g) via exp(s-m)/w
//   probs = softmax(s + samples) via exp(s-m)*exp(samples-1)  [C2 = m+1]
// One CTA (256 thr) per row; 4 elems per thread (float4).
// ============================================================================
__global__ __launch_bounds__(256)
void softmax_kernel(const float* __restrict__ gum)
{
    __shared__ float red[8];
    __shared__ float bcast;
    const int tid = threadIdx.x;
    const int lane = tid & 31, wid = tid >> 5;

    const size_t row = (size_t)blockIdx.y * SS + blockIdx.x;  // bh*S + l
    float* srow = g_sc + row * SS;
    const float* urow = gum + row * SS;

    float4 s = *(const float4*)&srow[tid * 4];
    float4 u = *(const float4*)&urow[tid * 4];

    // ---- reduction 1: row max of scores ----
    float m = fmaxf(fmaxf(s.x, s.y), fmaxf(s.z, s.w));
#pragma unroll
    for (int o = 16; o; o >>= 1) m = fmaxf(m, __shfl_xor_sync(0xffffffffu, m, o));
    if (lane == 0) red[wid] = m;
    __syncthreads();
    if (tid == 0) {
        float r = red[0];
#pragma unroll
        for (int i = 1; i < 8; i++) r = fmaxf(r, red[i]);
        bcast = r;
    }
    __syncthreads();
    m = bcast;

    float t0 = __expf(s.x - m), t1 = __expf(s.y - m);
    float t2 = __expf(s.z - m), t3 = __expf(s.w - m);
    // accurate logf: MUFU LG2 abs error corrupts w when u -> 1 (w ~ 1e-6)
    float w0 = 1e-10f - logf(u.x + 1e-10f);
    float w1 = 1e-10f - logf(u.y + 1e-10f);
    float w2 = 1e-10f - logf(u.z + 1e-10f);
    float w3 = 1e-10f - logf(u.w + 1e-10f);
    float n0 = __fdividef(t0, w0), n1 = __fdividef(t1, w1);
    float n2 = __fdividef(t2, w2), n3 = __fdividef(t3, w3);

    // ---- reduction 2: sum of samples numerators ----
    float sm1 = (n0 + n1) + (n2 + n3);
    __syncthreads();  // protect red[] reuse
#pragma unroll
    for (int o = 16; o; o >>= 1) sm1 += __shfl_xor_sync(0xffffffffu, sm1, o);
    if (lane == 0) red[wid] = sm1;
    __syncthreads();
    if (tid == 0) {
        float r = red[0];
#pragma unroll
        for (int i = 1; i < 8; i++) r += red[i];
        bcast = r;
    }
    __syncthreads();
    float inv1 = __fdividef(1.0f, bcast);

    // probs numerator: exp(s + samples - (m+1)) = t * exp(samples - 1)
    float p0 = t0 * __expf(fmaf(n0, inv1, -1.0f));
    float p1 = t1 * __expf(fmaf(n1, inv1, -1.0f));
    float p2 = t2 * __expf(fmaf(n2, inv1, -1.0f));
    float p3 = t3 * __expf(fmaf(n3, inv1, -1.0f));

    // ---- reduction 3: sum of probs numerators ----
    float sm2 = (p0 + p1) + (p2 + p3);
    __syncthreads();
#pragma unroll
    for (int o = 16; o; o >>= 1) sm2 += __shfl_xor_sync(0xffffffffu, sm2, o);
    if (lane == 0) red[wid] = sm2;
    __syncthreads();
    if (tid == 0) {
        float r = red[0];
#pragma unroll
        for (int i = 1; i < 8; i++) r += red[i];
        bcast = r;
    }
    __syncthreads();
    float inv2 = __fdividef(1.0f, bcast);

    float4 o4;
    o4.x = p0 * inv2; o4.y = p1 * inv2; o4.z = p2 * inv2; o4.w = p3 * inv2;
    *(float4*)&srow[tid * 4] = o4;
}

// ============================================================================
// K4: out[b,l,h*64+d] = sum_r probs[bh,l,r] * v[bh,r,d]
// BM=128, BN=64(full), BK=32; 256 threads, 8x4 per thread.
// ============================================================================
__global__ __launch_bounds__(256, 2)
void pv_kernel(float* __restrict__ out)
{
    __shared__ float Ps[32 * 129];  // [k][li], pad 129 -> conflict-free
    __shared__ float Vs[32 * 64];   // [k][d]

    const int tid = threadIdx.x;
    const int tx = tid & 15, ty = tid >> 4;
    const int bh = blockIdx.y;
    const int l0 = blockIdx.x * 128;
    const int b_ = bh >> 4, h = bh & 15;

    const float* P = g_sc + (size_t)bh * SS * SS;
    const float* V = g_v + (size_t)bh * SS * HDD;

    float acc[8][4];
#pragma unroll
    for (int i = 0; i < 8; i++)
#pragma unroll
        for (int j = 0; j < 4; j++) acc[i][j] = 0.f;

    for (int k0 = 0; k0 < 1024; k0 += 32) {
#pragma unroll
        for (int rep = 0; rep < 4; rep++) {
            int idx = rep * 256 + tid;      // 0..1023
            int li = idx >> 3;              // 0..127 (coalesced global)
            int k4 = (idx & 7) * 4;         // 0..28
            float4 vp = *(const float4*)&P[(size_t)(l0 + li) * SS + k0 + k4];
            Ps[(k4 + 0) * 129 + li] = vp.x; Ps[(k4 + 1) * 129 + li] = vp.y;
            Ps[(k4 + 2) * 129 + li] = vp.z; Ps[(k4 + 3) * 129 + li] = vp.w;
        }
#pragma unroll
        for (int rep = 0; rep < 2; rep++) {
            int idx = rep * 256 + tid;      // 0..511
            int kk = idx >> 4;              // 0..31
            int d4 = (idx & 15) * 4;
            *(float4*)&Vs[kk * 64 + d4] =
                *(const float4*)&V[(size_t)(k0 + kk) * 64 + d4];
        }
        __syncthreads();
#pragma unroll 4
        for (int k = 0; k < 32; k++) {
            float a[8];
#pragma unroll
            for (int u = 0; u < 8; u++) a[u] = Ps[k * 129 + ty * 8 + u];
            float4 bv4 = *(const float4*)&Vs[k * 64 + tx * 4];
#pragma unroll
            for (int i = 0; i < 8; i++) {
                acc[i][0] = fmaf(a[i], bv4.x, acc[i][0]);
                acc[i][1] = fmaf(a[i], bv4.y, acc[i][1]);
                acc[i][2] = fmaf(a[i], bv4.z, acc[i][2]);
                acc[i][3] = fmaf(a[i], bv4.w, acc[i][3]);
            }
        }
        __syncthreads();
    }

#pragma unroll
    for (int i = 0; i < 8; i++) {
        int l = l0 + ty * 8 + i;
        float4 o4;
        o4.x = acc[i][0]; o4.y = acc[i][1]; o4.z = acc[i][2]; o4.w = acc[i][3];
        *(float4*)&out[((size_t)(b_ * SS) + l) * DD + h * 64 + tx * 4] = o4;
    }
}

// ============================================================================
extern "C" void kernel_launch(void* const* d_in, const int* in_sizes, int n_in,
                              void* d_out, int out_size)
{
    const float* hidden = (const float*)d_in[0];
    const float* mask   = (const float*)d_in[1];
    const float* gum    = (const float*)d_in[2];
    const float* Wq     = (const float*)d_in[3];
    const float* bq     = (const float*)d_in[4];
    const float* Wk     = (const float*)d_in[5];
    const float* bk     = (const float*)d_in[6];
    const float* Wv     = (const float*)d_in[7];
    const float* bv     = (const float*)d_in[8];
    const float* de     = (const float*)d_in[9];
    float* out = (float*)d_out;

    qkv_kernel<<<dim3(8, 16, 3), 256>>>(hidden, Wq, bq, Wk, bk, Wv, bv);
    scores_kernel<<<dim3(8, 8, 32), 256>>>(mask, de);
    softmax_kernel<<<dim3(1024, 32), 256>>>(gum);
    pv_kernel<<<dim3(8, 32), 256>>>(out);
}

// round 3
// speedup vs baseline: 1.9274x; 1.9262x over previous
#include <cuda_runtime.h>
#include <cuda_bf16.h>
#include <math.h>

typedef unsigned int u32;
typedef __nv_bfloat16 bf16;

#define SS 1024
#define HH 16
#define HDD 64
#define NBH 32

// ---------------- scratch (device globals) ----------------
__device__ bf16 g_xhi[2048*1024], g_xlo[2048*1024];
__device__ bf16 g_whi[3*1024*1024], g_wlo[3*1024*1024];
__device__ bf16 g_dehi[2047*64];
__device__ bf16 g_qhi[NBH*SS*HDD], g_qlo[NBH*SS*HDD];
__device__ bf16 g_khi[NBH*SS*HDD], g_klo[NBH*SS*HDD];
__device__ bf16 g_vhi[NBH*SS*HDD], g_vlo[NBH*SS*HDD];
__device__ bf16 g_phi[(size_t)NBH*SS*SS], g_plo[(size_t)NBH*SS*SS];
__device__ float g_sc[(size_t)NBH*SS*SS];

// ---------------- helpers ----------------
__device__ __forceinline__ u32 sptr(const void* p){ return (u32)__cvta_generic_to_shared(p); }
__device__ __forceinline__ void ldsm4(u32& r0,u32& r1,u32& r2,u32& r3,u32 a){
    asm volatile("ldmatrix.sync.aligned.m8n8.x4.shared.b16 {%0,%1,%2,%3},[%4];"
                 :"=r"(r0),"=r"(r1),"=r"(r2),"=r"(r3):"r"(a));
}
__device__ __forceinline__ void ldsm4t(u32& r0,u32& r1,u32& r2,u32& r3,u32 a){
    asm volatile("ldmatrix.sync.aligned.m8n8.x4.trans.shared.b16 {%0,%1,%2,%3},[%4];"
                 :"=r"(r0),"=r"(r1),"=r"(r2),"=r"(r3):"r"(a));
}
__device__ __forceinline__ void mma16816(float (&c)[4], const u32 (&a)[4], u32 b0, u32 b1){
    asm volatile("mma.sync.aligned.m16n8k16.row.col.f32.bf16.bf16.f32 "
                 "{%0,%1,%2,%3},{%4,%5,%6,%7},{%8,%9},{%0,%1,%2,%3};"
                 :"+f"(c[0]),"+f"(c[1]),"+f"(c[2]),"+f"(c[3])
                 :"r"(a[0]),"r"(a[1]),"r"(a[2]),"r"(a[3]),"r"(b0),"r"(b1));
}
__device__ __forceinline__ void split2(float v, bf16& h, bf16& l){
    h = __float2bfloat16_rn(v);
    l = __float2bfloat16_rn(v - __bfloat162float(h));
}

// ============================================================================
// K0: fp32 -> bf16 (hi,lo) splits. which: 0=X, 1..3=Wq/Wk/Wv, 4=dist_emb (hi only)
// ============================================================================
__global__ __launch_bounds__(256)
void cvt_kernel(const float* __restrict__ src, int which, int n4)
{
    int i = blockIdx.x * 256 + threadIdx.x;
    if (i >= n4) return;
    bf16 *hi, *lo = nullptr;
    switch (which) {
        case 0: hi = g_xhi;           lo = g_xlo;           break;
        case 1: hi = g_whi;           lo = g_wlo;           break;
        case 2: hi = g_whi + 1048576; lo = g_wlo + 1048576; break;
        case 3: hi = g_whi + 2097152; lo = g_wlo + 2097152; break;
        default:hi = g_dehi;                                 break;
    }
    float4 v = *(const float4*)(src + (size_t)i * 4);
    float vv[4] = {v.x, v.y, v.z, v.w};
    bf16 h[4], l[4];
#pragma unroll
    for (int j = 0; j < 4; j++) split2(vv[j], h[j], l[j]);
    __nv_bfloat162 h0; h0.x=h[0]; h0.y=h[1];
    __nv_bfloat162 h1; h1.x=h[2]; h1.y=h[3];
    *(uint2*)(hi + (size_t)i*4) = make_uint2(*(u32*)&h0, *(u32*)&h1);
    if (lo) {
        __nv_bfloat162 l0; l0.x=l[0]; l0.y=l[1];
        __nv_bfloat162 l1; l1.x=l[2]; l1.y=l[3];
        *(uint2*)(lo + (size_t)i*4) = make_uint2(*(u32*)&l0, *(u32*)&l1);
    }
}

// ============================================================================
// K1: q/k/v = X @ W^T + b (bf16 x3 mma), writes hi/lo bf16 in [B,H,S,HD].
// CTA 128m x 64n, BK=32, 8 warps (4m x 2n), warp 32x32.
// ============================================================================
__global__ __launch_bounds__(256)
void qkv_mma(const float* __restrict__ bq, const float* __restrict__ bk,
             const float* __restrict__ bv)
{
    __shared__ __align__(16) bf16 sA[2][128*40];
    __shared__ __align__(16) bf16 sB[2][64*40];

    const int tid = threadIdx.x, wid = tid>>5, lane = tid&31;
    const int warpM = wid>>1, warpN = wid&1;
    const int z = blockIdx.z, n0 = blockIdx.x*64, m0 = blockIdx.y*128;
    const int lr = lane&15, lc8 = (lane>>4)*8, g = lane>>2, t = lane&3;

    const bf16* Bh = g_whi + (size_t)z*1048576;
    const bf16* Bl = g_wlo + (size_t)z*1048576;
    const float* bias = (z==0)?bq:(z==1)?bk:bv;
    bf16* dhi = (z==0)?g_qhi:(z==1)?g_khi:g_vhi;
    bf16* dlo = (z==0)?g_qlo:(z==1)?g_klo:g_vlo;

    float acc[2][4][4];
#pragma unroll
    for (int i=0;i<2;i++)
#pragma unroll
        for (int j=0;j<4;j++)
#pragma unroll
            for (int c=0;c<4;c++) acc[i][j][c]=0.f;

    for (int k0 = 0; k0 < 1024; k0 += 32) {
#pragma unroll
        for (int rep=0;rep<2;rep++){
            int idx = rep*256+tid, r = idx>>2, s = idx&3;
            *(uint4*)&sA[0][r*40+s*8] = *(const uint4*)&g_xhi[(size_t)(m0+r)*1024 + k0 + s*8];
            *(uint4*)&sA[1][r*40+s*8] = *(const uint4*)&g_xlo[(size_t)(m0+r)*1024 + k0 + s*8];
        }
        { int r = tid>>2, s = tid&3;
          *(uint4*)&sB[0][r*40+s*8] = *(const uint4*)&Bh[(size_t)(n0+r)*1024 + k0 + s*8];
          *(uint4*)&sB[1][r*40+s*8] = *(const uint4*)&Bl[(size_t)(n0+r)*1024 + k0 + s*8]; }
        __syncthreads();
#pragma unroll
        for (int kb=0;kb<32;kb+=16){
            u32 ah[2][4], al[2][4], bhr[4][2], blr[4][2];
#pragma unroll
            for (int mt=0;mt<2;mt++){
                ldsm4(ah[mt][0],ah[mt][1],ah[mt][2],ah[mt][3],
                      sptr(&sA[0][(warpM*32+mt*16+lr)*40 + kb + lc8]));
                ldsm4(al[mt][0],al[mt][1],al[mt][2],al[mt][3],
                      sptr(&sA[1][(warpM*32+mt*16+lr)*40 + kb + lc8]));
            }
#pragma unroll
            for (int gg=0;gg<2;gg++){
                u32 r0,r1,r2,r3;
                ldsm4(r0,r1,r2,r3, sptr(&sB[0][(warpN*32+gg*16+lr)*40 + kb + lc8]));
                bhr[2*gg][0]=r0; bhr[2*gg][1]=r2; bhr[2*gg+1][0]=r1; bhr[2*gg+1][1]=r3;
                ldsm4(r0,r1,r2,r3, sptr(&sB[1][(warpN*32+gg*16+lr)*40 + kb + lc8]));
                blr[2*gg][0]=r0; blr[2*gg][1]=r2; blr[2*gg+1][0]=r1; blr[2*gg+1][1]=r3;
            }
#pragma unroll
            for (int mt=0;mt<2;mt++)
#pragma unroll
                for (int nt=0;nt<4;nt++){
                    mma16816(acc[mt][nt], ah[mt], bhr[nt][0], bhr[nt][1]);
                    mma16816(acc[mt][nt], ah[mt], blr[nt][0], blr[nt][1]);
                    mma16816(acc[mt][nt], al[mt], bhr[nt][0], bhr[nt][1]);
                }
        }
        __syncthreads();
    }

#pragma unroll
    for (int mt=0;mt<2;mt++)
#pragma unroll
        for (int nt=0;nt<4;nt++){
            int ncol = n0 + warpN*32 + nt*8 + 2*t;
            float b0 = bias[ncol], b1 = bias[ncol+1];
            int h = ncol>>6, dd = ncol&63;
#pragma unroll
            for (int rr=0;rr<2;rr++){
                int m = m0 + warpM*32 + mt*16 + g + rr*8;
                int b_ = m>>10, l = m&1023;
                float v0 = acc[mt][nt][rr*2+0] + b0;
                float v1 = acc[mt][nt][rr*2+1] + b1;
                bf16 h0,l0,h1,l1; split2(v0,h0,l0); split2(v1,h1,l1);
                size_t o = (((size_t)(b_*HH + h))*SS + l)*HDD + dd;
                __nv_bfloat162 hp; hp.x=h0; hp.y=h1;
                __nv_bfloat162 lp; lp.x=l0; lp.y=l1;
                *(__nv_bfloat162*)&dhi[o] = hp;
                *(__nv_bfloat162*)&dlo[o] = lp;
            }
        }
}

// ============================================================================
// K2: scores = (q k^T)[x3] + Toeplitz(Q DE^T)[x1], *0.125 + mask -> f32
// CTA 128x128, 8 warps (2m x 4n), warp 64x32. pe via 4 T-chunks of 64 cols.
// ============================================================================
__global__ __launch_bounds__(256)
void scores_mma(const float* __restrict__ mask)
{
    __shared__ __align__(16) char sm[49152];
    bf16*  sQh = (bf16*)sm;             // 128*40
    bf16*  sQl = (bf16*)(sm+10240);
    bf16*  sKh = (bf16*)(sm+20480);
    bf16*  sKl = (bf16*)(sm+30720);
    bf16*  sDE = (bf16*)(sm+10240);     // phase2: 64*40
    float* sT  = (float*)(sm+15360);    // 128*66 f32

    const int tid = threadIdx.x, wid = tid>>5, lane = tid&31;
    const int warpM = wid>>2, warpN = wid&3;
    const int bh = blockIdx.z, l0 = blockIdx.y*128, r0 = blockIdx.x*128;
    const int b_ = bh>>4;
    const int jb = l0 - r0 + 896;
    const int lr = lane&15, lc8 = (lane>>4)*8, g = lane>>2, t = lane&3;

    const bf16* qh = g_qhi + (size_t)bh*SS*HDD;
    const bf16* ql = g_qlo + (size_t)bh*SS*HDD;
    const bf16* kh = g_khi + (size_t)bh*SS*HDD;
    const bf16* kl = g_klo + (size_t)bh*SS*HDD;

    float acc[4][4][4];
#pragma unroll
    for (int i=0;i<4;i++)
#pragma unroll
        for (int j=0;j<4;j++)
#pragma unroll
            for (int c=0;c<4;c++) acc[i][j][c]=0.f;

    // ---- phase 1: qk^T x3 ----
    for (int kc=0;kc<2;kc++){
        int k0 = kc*32;
        __syncthreads();
#pragma unroll
        for (int rep=0;rep<2;rep++){
            int idx = rep*256+tid, r = idx>>2, s = idx&3;
            *(uint4*)&sQh[r*40+s*8] = *(const uint4*)&qh[(size_t)(l0+r)*64 + k0 + s*8];
            *(uint4*)&sQl[r*40+s*8] = *(const uint4*)&ql[(size_t)(l0+r)*64 + k0 + s*8];
            *(uint4*)&sKh[r*40+s*8] = *(const uint4*)&kh[(size_t)(r0+r)*64 + k0 + s*8];
            *(uint4*)&sKl[r*40+s*8] = *(const uint4*)&kl[(size_t)(r0+r)*64 + k0 + s*8];
        }
        __syncthreads();
#pragma unroll
        for (int kb=0;kb<32;kb+=16){
            u32 ah[4][4], al[4][4], bhr[4][2], blr[4][2];
#pragma unroll
            for (int mt=0;mt<4;mt++){
                ldsm4(ah[mt][0],ah[mt][1],ah[mt][2],ah[mt][3],
                      sptr(&sQh[(warpM*64+mt*16+lr)*40 + kb + lc8]));
                ldsm4(al[mt][0],al[mt][1],al[mt][2],al[mt][3],
                      sptr(&sQl[(warpM*64+mt*16+lr)*40 + kb + lc8]));
            }
#pragma unroll
            for (int gg=0;gg<2;gg++){
                u32 r0r,r1r,r2r,r3r;
                ldsm4(r0r,r1r,r2r,r3r, sptr(&sKh[(warpN*32+gg*16+lr)*40 + kb + lc8]));
                bhr[2*gg][0]=r0r; bhr[2*gg][1]=r2r; bhr[2*gg+1][0]=r1r; bhr[2*gg+1][1]=r3r;
                ldsm4(r0r,r1r,r2r,r3r, sptr(&sKl[(warpN*32+gg*16+lr)*40 + kb + lc8]));
                blr[2*gg][0]=r0r; blr[2*gg][1]=r2r; blr[2*gg+1][0]=r1r; blr[2*gg+1][1]=r3r;
            }
#pragma unroll
            for (int mt=0;mt<4;mt++)
#pragma unroll
                for (int nt=0;nt<4;nt++){
                    mma16816(acc[mt][nt], ah[mt], bhr[nt][0], bhr[nt][1]);
                    mma16816(acc[mt][nt], ah[mt], blr[nt][0], blr[nt][1]);
                    mma16816(acc[mt][nt], al[mt], bhr[nt][0], bhr[nt][1]);
                }
        }
    }

    // ---- phase 2: pe via T = Q DE^T (x1), 4 chunks of 64 t-cols ----
    for (int c=0;c<4;c++){
        int t0c = 64*c;
        float Tacc[4][2][4];
#pragma unroll
        for (int i=0;i<4;i++)
#pragma unroll
            for (int j=0;j<2;j++)
#pragma unroll
                for (int q=0;q<4;q++) Tacc[i][j][q]=0.f;
        for (int kc=0;kc<2;kc++){
            int k0 = kc*32;
            __syncthreads();
#pragma unroll
            for (int rep=0;rep<2;rep++){
                int idx = rep*256+tid, r = idx>>2, s = idx&3;
                *(uint4*)&sQh[r*40+s*8] = *(const uint4*)&qh[(size_t)(l0+r)*64 + k0 + s*8];
            }
            { int r = tid>>2, s = tid&3;
              int der = jb + t0c + r; if (der > 2046) der = 2046;
              *(uint4*)&sDE[r*40+s*8] = *(const uint4*)&g_dehi[(size_t)der*64 + k0 + s*8]; }
            __syncthreads();
#pragma unroll
            for (int kb=0;kb<32;kb+=16){
                u32 ah[4][4];
#pragma unroll
                for (int mt=0;mt<4;mt++)
                    ldsm4(ah[mt][0],ah[mt][1],ah[mt][2],ah[mt][3],
                          sptr(&sQh[(warpM*64+mt*16+lr)*40 + kb + lc8]));
                u32 r0r,r1r,r2r,r3r;
                ldsm4(r0r,r1r,r2r,r3r, sptr(&sDE[(warpN*16+lr)*40 + kb + lc8]));
#pragma unroll
                for (int mt=0;mt<4;mt++){
                    mma16816(Tacc[mt][0], ah[mt], r0r, r2r);
                    mma16816(Tacc[mt][1], ah[mt], r1r, r3r);
                }
            }
        }
        __syncthreads();  // all mma smem reads done before sT overwrite next chunk
#pragma unroll
        for (int mt=0;mt<4;mt++)
#pragma unroll
            for (int n2=0;n2<2;n2++){
                int col = warpN*16 + n2*8 + 2*t;
                int rw = warpM*64 + mt*16 + g;
                *(float2*)&sT[rw*66 + col]     = make_float2(Tacc[mt][n2][0], Tacc[mt][n2][1]);
                *(float2*)&sT[(rw+8)*66 + col] = make_float2(Tacc[mt][n2][2], Tacc[mt][n2][3]);
            }
        __syncthreads();
#pragma unroll
        for (int mt=0;mt<4;mt++){
            int ib = warpM*64 + mt*16 + g;
#pragma unroll
            for (int nt=0;nt<4;nt++){
                int jb0 = warpN*32 + nt*8 + 2*t;
#pragma unroll
                for (int cr=0;cr<4;cr++){
                    int i = ib + (cr>>1)*8, j = jb0 + (cr&1);
                    int tt = i - j + 127 - t0c;
                    if ((unsigned)tt < 64u) acc[mt][nt][cr] += sT[i*66 + tt];
                }
            }
        }
        __syncthreads();
    }

    // ---- epilogue ----
    float* outp = g_sc + (size_t)bh*SS*SS;
#pragma unroll
    for (int mt=0;mt<4;mt++){
        int i0 = l0 + warpM*64 + mt*16 + g;
#pragma unroll
        for (int nt=0;nt<4;nt++){
            int jc = r0 + warpN*32 + nt*8 + 2*t;
            float2 mk = *(const float2*)&mask[b_*SS + jc];
            *(float2*)&outp[(size_t)i0*SS + jc] =
                make_float2(fmaf(acc[mt][nt][0],0.125f,mk.x), fmaf(acc[mt][nt][1],0.125f,mk.y));
            *(float2*)&outp[(size_t)(i0+8)*SS + jc] =
                make_float2(fmaf(acc[mt][nt][2],0.125f,mk.x), fmaf(acc[mt][nt][3],0.125f,mk.y));
        }
    }
}

// ============================================================================
// K3: stochastic double softmax; reads f32 scores, writes bf16 hi/lo probs.
// ============================================================================
__global__ __launch_bounds__(256)
void softmax_kernel(const float* __restrict__ gum)
{
    __shared__ float red[8];
    __shared__ float bcast;
    const int tid = threadIdx.x, lane = tid&31, wid = tid>>5;
    const size_t row = (size_t)blockIdx.y * SS + blockIdx.x;
    const float* srow = g_sc + row * SS;
    const float* urow = gum + row * SS;

    float4 s = *(const float4*)&srow[tid*4];
    float4 u = *(const float4*)&urow[tid*4];

    float m = fmaxf(fmaxf(s.x,s.y), fmaxf(s.z,s.w));
#pragma unroll
    for (int o=16;o;o>>=1) m = fmaxf(m, __shfl_xor_sync(0xffffffffu,m,o));
    if (lane==0) red[wid]=m;
    __syncthreads();
    if (tid==0){ float r=red[0];
#pragma unroll
        for (int i=1;i<8;i++) r=fmaxf(r,red[i]); bcast=r; }
    __syncthreads();
    m = bcast;

    float t0=__expf(s.x-m), t1=__expf(s.y-m), t2=__expf(s.z-m), t3=__expf(s.w-m);
    float w0 = 1e-10f - logf(u.x + 1e-10f);
    float w1 = 1e-10f - logf(u.y + 1e-10f);
    float w2 = 1e-10f - logf(u.z + 1e-10f);
    float w3 = 1e-10f - logf(u.w + 1e-10f);
    float n0=__fdividef(t0,w0), n1=__fdividef(t1,w1);
    float n2=__fdividef(t2,w2), n3=__fdividef(t3,w3);

    float sm1 = (n0+n1)+(n2+n3);
    __syncthreads();
#pragma unroll
    for (int o=16;o;o>>=1) sm1 += __shfl_xor_sync(0xffffffffu,sm1,o);
    if (lane==0) red[wid]=sm1;
    __syncthreads();
    if (tid==0){ float r=red[0];
#pragma unroll
        for (int i=1;i<8;i++) r+=red[i]; bcast=r; }
    __syncthreads();
    float inv1 = __fdividef(1.0f, bcast);

    float p0 = t0*__expf(fmaf(n0,inv1,-1.0f));
    float p1 = t1*__expf(fmaf(n1,inv1,-1.0f));
    float p2 = t2*__expf(fmaf(n2,inv1,-1.0f));
    float p3 = t3*__expf(fmaf(n3,inv1,-1.0f));

    float sm2 = (p0+p1)+(p2+p3);
    __syncthreads();
#pragma unroll
    for (int o=16;o;o>>=1) sm2 += __shfl_xor_sync(0xffffffffu,sm2,o);
    if (lane==0) red[wid]=sm2;
    __syncthreads();
    if (tid==0){ float r=red[0];
#pragma unroll
        for (int i=1;i<8;i++) r+=red[i]; bcast=r; }
    __syncthreads();
    float inv2 = __fdividef(1.0f, bcast);

    float v0=p0*inv2, v1=p1*inv2, v2=p2*inv2, v3=p3*inv2;
    bf16 h0,l0,h1,l1,h2,l2,h3,l3;
    split2(v0,h0,l0); split2(v1,h1,l1); split2(v2,h2,l2); split2(v3,h3,l3);
    __nv_bfloat162 ha; ha.x=h0; ha.y=h1;
    __nv_bfloat162 hb; hb.x=h2; hb.y=h3;
    __nv_bfloat162 la; la.x=l0; la.y=l1;
    __nv_bfloat162 lb; lb.x=l2; lb.y=l3;
    *(uint2*)&g_phi[row*SS + tid*4] = make_uint2(*(u32*)&ha, *(u32*)&hb);
    *(uint2*)&g_plo[row*SS + tid*4] = make_uint2(*(u32*)&la, *(u32*)&lb);
}

// ============================================================================
// K4: out = P @ V (bf16 x3 mma). CTA 128m x 64n, BK=32, 8 warps (4m x 2n).
// ============================================================================
__global__ __launch_bounds__(256)
void pv_mma(float* __restrict__ out)
{
    __shared__ __align__(16) bf16 sP[2][128*40];
    __shared__ __align__(16) bf16 sV[2][32*72];

    const int tid = threadIdx.x, wid = tid>>5, lane = tid&31;
    const int warpM = wid>>1, warpN = wid&1;
    const int bh = blockIdx.y, l0 = blockIdx.x*128;
    const int b_ = bh>>4, h = bh&15;
    const int lr = lane&15, lc8 = (lane>>4)*8, g = lane>>2, t = lane&3;

    const bf16* Ph = g_phi + (size_t)bh*SS*SS;
    const bf16* Pl = g_plo + (size_t)bh*SS*SS;
    const bf16* Vh = g_vhi + (size_t)bh*SS*HDD;
    const bf16* Vl = g_vlo + (size_t)bh*SS*HDD;

    float acc[2][4][4];
#pragma unroll
    for (int i=0;i<2;i++)
#pragma unroll
        for (int j=0;j<4;j++)
#pragma unroll
            for (int c=0;c<4;c++) acc[i][j][c]=0.f;

    for (int k0 = 0; k0 < 1024; k0 += 32) {
#pragma unroll
        for (int rep=0;rep<2;rep++){
            int idx = rep*256+tid, r = idx>>2, s = idx&3;
            *(uint4*)&sP[0][r*40+s*8] = *(const uint4*)&Ph[(size_t)(l0+r)*1024 + k0 + s*8];
            *(uint4*)&sP[1][r*40+s*8] = *(const uint4*)&Pl[(size_t)(l0+r)*1024 + k0 + s*8];
        }
        { int r = tid>>3, s = tid&7;
          *(uint4*)&sV[0][r*72+s*8] = *(const uint4*)&Vh[(size_t)(k0+r)*64 + s*8];
          *(uint4*)&sV[1][r*72+s*8] = *(const uint4*)&Vl[(size_t)(k0+r)*64 + s*8]; }
        __syncthreads();
#pragma unroll
        for (int kb=0;kb<32;kb+=16){
            u32 ah[2][4], al[2][4], bhr[4][2], blr[4][2];
#pragma unroll
            for (int mt=0;mt<2;mt++){
                ldsm4(ah[mt][0],ah[mt][1],ah[mt][2],ah[mt][3],
                      sptr(&sP[0][(warpM*32+mt*16+lr)*40 + kb + lc8]));
                ldsm4(al[mt][0],al[mt][1],al[mt][2],al[mt][3],
                      sptr(&sP[1][(warpM*32+mt*16+lr)*40 + kb + lc8]));
            }
#pragma unroll
            for (int gg=0;gg<2;gg++){
                u32 r0,r1,r2,r3;
                ldsm4t(r0,r1,r2,r3, sptr(&sV[0][(kb+lr)*72 + warpN*32 + gg*16 + lc8]));
                bhr[2*gg][0]=r0; bhr[2*gg][1]=r1; bhr[2*gg+1][0]=r2; bhr[2*gg+1][1]=r3;
                ldsm4t(r0,r1,r2,r3, sptr(&sV[1][(kb+lr)*72 + warpN*32 + gg*16 + lc8]));
                blr[2*gg][0]=r0; blr[2*gg][1]=r1; blr[2*gg+1][0]=r2; blr[2*gg+1][1]=r3;
            }
#pragma unroll
            for (int mt=0;mt<2;mt++)
#pragma unroll
                for (int nt=0;nt<4;nt++){
                    mma16816(acc[mt][nt], ah[mt], bhr[nt][0], bhr[nt][1]);
                    mma16816(acc[mt][nt], ah[mt], blr[nt][0], blr[nt][1]);
                    mma16816(acc[mt][nt], al[mt], bhr[nt][0], bhr[nt][1]);
                }
        }
        __syncthreads();
    }

#pragma unroll
    for (int mt=0;mt<2;mt++)
#pragma unroll
        for (int nt=0;nt<4;nt++){
            int dcol = warpN*32 + nt*8 + 2*t;
#pragma unroll
            for (int rr=0;rr<2;rr++){
                int l = l0 + warpM*32 + mt*16 + g + rr*8;
                *(float2*)&out[((size_t)(b_*SS)+l)*1024 + h*64 + dcol] =
                    make_float2(acc[mt][nt][rr*2+0], acc[mt][nt][rr*2+1]);
            }
        }
}

// ============================================================================
extern "C" void kernel_launch(void* const* d_in, const int* in_sizes, int n_in,
                              void* d_out, int out_size)
{
    const float* hidden = (const float*)d_in[0];
    const float* mask   = (const float*)d_in[1];
    const float* gum    = (const float*)d_in[2];
    const float* Wq     = (const float*)d_in[3];
    const float* Wk     = (const float*)d_in[5];
    const float* Wv     = (const float*)d_in[7];
    const float* bq     = (const float*)d_in[4];
    const float* bk     = (const float*)d_in[6];
    const float* bv     = (const float*)d_in[8];
    const float* de     = (const float*)d_in[9];
    float* out = (float*)d_out;

    cvt_kernel<<<2048, 256>>>(hidden, 0, 524288);
    cvt_kernel<<<1024, 256>>>(Wq, 1, 262144);
    cvt_kernel<<<1024, 256>>>(Wk, 2, 262144);
    cvt_kernel<<<1024, 256>>>(Wv, 3, 262144);
    cvt_kernel<<<128,  256>>>(de, 4, 32752);
    qkv_mma<<<dim3(16, 16, 3), 256>>>(bq, bk, bv);
    scores_mma<<<dim3(8, 8, 32), 256>>>(mask);
    softmax_kernel<<<dim3(1024, 32), 256>>>(gum);
    pv_mma<<<dim3(8, 32), 256>>>(out);
}